// round 2
// baseline (speedup 1.0000x reference)
#include <cuda_runtime.h>
#include <cstdint>
#include <cstddef>

// ---------------- problem constants (fixed by dataset) ----------------
static constexpr int Bc = 16;
static constexpr int Dc = 512;
static constexpr int Tc = 1500;
static constexpr int Nc = Bc * Tc;      // 24000 rows
static constexpr int Kc = 4096;         // codes
static constexpr int NCHUNKS = 75;      // column-reduce row chunks
static constexpr int RCHUNK  = Nc / NCHUNKS; // 320

// ---------------- device scratch (no allocations allowed) ----------------
__device__ float g_w[(size_t)Nc * Kc];  // unnormalized exp(-dist), ~393MB
__device__ float g_Z[Nc];               // row sums
__device__ float g_z2[Nc];              // ||z||^2 per row
__device__ float g_c2[Kc];              // ||c||^2 per code
__device__ int   g_nvalid[Bc];          // valid frames per batch
__device__ float g_partial[NCHUNKS][Kc];

// ---------------- kernel 0: init (zero Z, sniff lengths/stride, nvalid) ----------------
__global__ void k_init(const void* lenp, const void* stridep) {
    int i = blockIdx.x * blockDim.x + threadIdx.x;
    for (int n = i; n < Nc; n += blockDim.x * gridDim.x) g_Z[n] = 0.f;
    if (i == 0) {
        // sniff encoder_stride (int32 vs int64 scalar)
        long long s = 320;
        if (stridep) {
            long long v = *(const long long*)stridep;
            if (v > 0 && v < (1ll << 31)) s = v;
            else {
                int v32 = *(const int*)stridep;
                if (v32 > 0) s = v32;
            }
        }
        // sniff lengths dtype: genuine int64 values are all in [0, 2^31)
        const long long* l64 = (const long long*)lenp;
        const int*       l32 = (const int*)lenp;
        bool is64 = true;
        for (int b = 0; b < Bc; b++) {
            long long v = l64[b];
            if (v < 0 || v >= (1ll << 31)) { is64 = false; break; }
        }
        for (int b = 0; b < Bc; b++) {
            long long L = is64 ? l64[b] : (long long)l32[b];
            long long nv = L / s;
            if (nv > Tc) nv = Tc;
            if (nv < 0)  nv = 0;
            g_nvalid[b] = (int)nv;
        }
    }
}

// ---------------- kernel: z2[n] = sum_d feat[b,d,t]^2 ----------------
__global__ void k_z2(const float* __restrict__ feat) {
    int n = blockIdx.x * blockDim.x + threadIdx.x;
    if (n >= Nc) return;
    int b = n / Tc, t = n - b * Tc;
    const float* p = feat + (size_t)b * Dc * Tc + t;
    float s0 = 0.f, s1 = 0.f, s2 = 0.f, s3 = 0.f;
    #pragma unroll 4
    for (int d = 0; d < Dc; d += 4) {
        float v0 = p[(size_t)(d + 0) * Tc];
        float v1 = p[(size_t)(d + 1) * Tc];
        float v2 = p[(size_t)(d + 2) * Tc];
        float v3 = p[(size_t)(d + 3) * Tc];
        s0 += v0 * v0; s1 += v1 * v1; s2 += v2 * v2; s3 += v3 * v3;
    }
    g_z2[n] = (s0 + s1) + (s2 + s3);
}

// ---------------- kernel: c2[k] = sum_d codebook[k,d]^2 (warp per code) ----------------
__global__ void k_c2(const float* __restrict__ cb) {
    int warp = (blockIdx.x * blockDim.x + threadIdx.x) >> 5;
    int lane = threadIdx.x & 31;
    if (warp >= Kc) return;
    const float* r = cb + (size_t)warp * Dc;
    float s = 0.f;
    for (int d = lane; d < Dc; d += 32) { float v = r[d]; s += v * v; }
    #pragma unroll
    for (int o = 16; o; o >>= 1) s += __shfl_down_sync(0xffffffffu, s, o);
    if (lane == 0) g_c2[warp] = s;
}

// ---------------- kernel: fused GEMM + exp epilogue ----------------
// CTA tile: 128 rows x 128 codes, 256 threads, 8x8 per thread, D chunk = 16,
// double-buffered SMEM with transposed layouts for float4 LDS.
#define BD 16
__global__ __launch_bounds__(256, 2)
void k_gemm(const float* __restrict__ feat, const float* __restrict__ cb) {
    const int tid = threadIdx.x;
    const int k0 = blockIdx.x * 128;
    const int n0 = blockIdx.y * 128;

    // skip CTA if all 128 rows are masked out
    __shared__ int s_any;
    if (tid == 0) s_any = 0;
    __syncthreads();
    if (tid < 128) {
        int n = n0 + tid;
        if (n < Nc) {
            int b = n / Tc, t = n - b * Tc;
            if (t < g_nvalid[b]) s_any = 1;
        }
    }
    __syncthreads();
    if (!s_any) return;

    __shared__ __align__(16) float zs[2][BD][128];
    __shared__ __align__(16) float cs[2][BD][132];   // pad to 132 for store conflicts

    // ---- global load mapping ----
    const int zrow = tid & 127;       // z: row, d-lane
    const int zd   = tid >> 7;        // 0/1
    const int crow = tid & 15;        // c: d-lane (coalesced along D)
    const int ccol = tid >> 4;        // base code col (0..15)

    int n = n0 + zrow;
    bool zvalid = n < Nc;
    int zb = zvalid ? (n / Tc) : 0;
    int zt = zvalid ? (n - zb * Tc) : 0;
    const size_t zbase = (size_t)zb * Dc * Tc + zt;   // + d*Tc

    float zr[8], cr[8];

    // prefetch chunk 0
    {
        const int d0 = 0;
        #pragma unroll
        for (int j = 0; j < 8; j++) {
            int d = d0 + j * 2 + zd;
            zr[j] = zvalid ? feat[zbase + (size_t)d * Tc] : 0.f;
        }
        #pragma unroll
        for (int j = 0; j < 8; j++) {
            int col = j * 16 + ccol;
            cr[j] = cb[(size_t)(k0 + col) * Dc + d0 + crow];
        }
    }
    #pragma unroll
    for (int j = 0; j < 8; j++) zs[0][j * 2 + zd][zrow] = zr[j];
    #pragma unroll
    for (int j = 0; j < 8; j++) cs[0][crow][j * 16 + ccol] = cr[j];
    __syncthreads();

    const int ty = tid >> 4;  // rows ty*8
    const int tx = tid & 15;  // cols tx*8
    float acc[8][8];
    #pragma unroll
    for (int i = 0; i < 8; i++)
        #pragma unroll
        for (int j = 0; j < 8; j++) acc[i][j] = 0.f;

    const int NITER = Dc / BD;  // 32
    for (int it = 0; it < NITER; ++it) {
        const int buf = it & 1;
        if (it + 1 < NITER) {
            const int d0 = (it + 1) * BD;
            #pragma unroll
            for (int j = 0; j < 8; j++) {
                int d = d0 + j * 2 + zd;
                zr[j] = zvalid ? feat[zbase + (size_t)d * Tc] : 0.f;
            }
            #pragma unroll
            for (int j = 0; j < 8; j++) {
                int col = j * 16 + ccol;
                cr[j] = cb[(size_t)(k0 + col) * Dc + d0 + crow];
            }
        }
        #pragma unroll
        for (int d = 0; d < BD; d++) {
            float a[8], b8[8];
            *(float4*)&a[0]  = *(const float4*)&zs[buf][d][ty * 8];
            *(float4*)&a[4]  = *(const float4*)&zs[buf][d][ty * 8 + 4];
            *(float4*)&b8[0] = *(const float4*)&cs[buf][d][tx * 8];
            *(float4*)&b8[4] = *(const float4*)&cs[buf][d][tx * 8 + 4];
            #pragma unroll
            for (int i = 0; i < 8; i++)
                #pragma unroll
                for (int j = 0; j < 8; j++)
                    acc[i][j] = fmaf(a[i], b8[j], acc[i][j]);
        }
        if (it + 1 < NITER) {
            const int nb = buf ^ 1;
            #pragma unroll
            for (int j = 0; j < 8; j++) zs[nb][j * 2 + zd][zrow] = zr[j];
            #pragma unroll
            for (int j = 0; j < 8; j++) cs[nb][crow][j * 16 + ccol] = cr[j];
        }
        __syncthreads();
    }

    // ---- epilogue: w = exp(-sqrt(max(z2+c2-2*dot,1e-12))), row sums, store ----
    #pragma unroll
    for (int i = 0; i < 8; i++) {
        int n_ = n0 + ty * 8 + i;
        if (n_ >= Nc) continue;
        float zz = g_z2[n_];
        float wv[8];
        float rs = 0.f;
        #pragma unroll
        for (int j = 0; j < 8; j++) {
            int k = k0 + tx * 8 + j;
            float d2 = zz + g_c2[k] - 2.f * acc[i][j];
            float dist = __fsqrt_rn(fmaxf(d2, 1e-12f));
            float w = __expf(-dist);
            wv[j] = w;
            rs += w;
        }
        float* dst = &g_w[(size_t)n_ * Kc + k0 + tx * 8];
        *(float4*)&dst[0] = make_float4(wv[0], wv[1], wv[2], wv[3]);
        *(float4*)&dst[4] = make_float4(wv[4], wv[5], wv[6], wv[7]);
        // reduce rs across the 16 tx lanes (contiguous half... 16-lane groups)
        #pragma unroll
        for (int o = 8; o; o >>= 1) rs += __shfl_down_sync(0xffffffffu, rs, o, 16);
        if (tx == 0) atomicAdd(&g_Z[n_], rs);
    }
}

// ---------------- kernel: column reduce -> per-chunk partial code_dist ----------------
__global__ void k_colreduce() {
    int k = blockIdx.x * blockDim.x + threadIdx.x;   // 0..4095
    int n = blockIdx.y * RCHUNK;
    int b = n / Tc, t = n - b * Tc;
    int nv = g_nvalid[b];
    float acc = 0.f;
    for (int i = 0; i < RCHUNK; i++, n++, t++) {
        if (t >= Tc) { t = 0; b++; nv = g_nvalid[b]; }
        if (t < nv) {
            float Zn = g_Z[n];
            float w = g_w[(size_t)n * Kc + k];
            acc += __fdividef(w, Zn);
        }
    }
    g_partial[blockIdx.y][k] = acc;
}

// ---------------- kernel: final entropy ----------------
__device__ __forceinline__ float blockSum(float v) {
    __shared__ float sh[32];
    int lane = threadIdx.x & 31, w = threadIdx.x >> 5;
    #pragma unroll
    for (int o = 16; o; o >>= 1) v += __shfl_down_sync(0xffffffffu, v, o);
    if (!lane) sh[w] = v;
    __syncthreads();
    float r = 0.f;
    if (w == 0) {
        r = (lane < (blockDim.x >> 5)) ? sh[lane] : 0.f;
        #pragma unroll
        for (int o = 16; o; o >>= 1) r += __shfl_down_sync(0xffffffffu, r, o);
        if (!lane) sh[0] = r;
    }
    __syncthreads();
    float out = sh[0];
    __syncthreads();
    return out;
}

__global__ void k_final(float* out) {
    const int tid = threadIdx.x;   // 1024 threads
    float cd[4];
    #pragma unroll
    for (int j = 0; j < 4; j++) {
        int k = tid + j * 1024;
        float s = 0.f;
        for (int c = 0; c < NCHUNKS; c++) s += g_partial[c][k];
        cd[j] = s;
    }
    float tot = (cd[0] + cd[1]) + (cd[2] + cd[3]);
    float S = blockSum(tot);
    float denom = S + 1e-8f;
    float e = 0.f;
    #pragma unroll
    for (int j = 0; j < 4; j++) {
        float p = cd[j] / denom;
        e += p * logf(p + 1e-8f);      // entropy = -sum(...)
    }
    float E = blockSum(e);
    if (tid == 0) out[0] = 1.f + E / logf((float)Kc);
}

// ---------------- launch ----------------
extern "C" void kernel_launch(void* const* d_in, const int* in_sizes, int n_in,
                              void* d_out, int out_size) {
    const float* feat = (const float*)d_in[0];
    const float* cb   = (const float*)d_in[1];
    const void*  lenp = d_in[2];
    const void*  stridep = (n_in > 3) ? d_in[3] : nullptr;

    k_init<<<94, 256>>>(lenp, stridep);
    k_z2<<<(Nc + 255) / 256, 256>>>(feat);
    k_c2<<<Kc / 8, 256>>>(cb);            // 8 warps/block, warp per code

    dim3 gg(Kc / 128, (Nc + 127) / 128);  // 32 x 188
    k_gemm<<<gg, 256>>>(feat, cb);

    dim3 gr(Kc / 256, NCHUNKS);           // 16 x 75
    k_colreduce<<<gr, 256>>>();

    k_final<<<1, 1024>>>((float*)d_out);
    (void)in_sizes; (void)out_size;
}

// round 5
// speedup vs baseline: 4.1118x; 4.1118x over previous
#include <cuda_runtime.h>
#include <cuda_bf16.h>
#include <cstdint>
#include <cstddef>

// ---------------- problem constants ----------------
static constexpr int Bc = 16;
static constexpr int Dc = 512;
static constexpr int Tc = 1500;
static constexpr int Nc = Bc * Tc;              // 24000
static constexpr int Kc = 4096;
static constexpr int ROWB = 128;                // CTA row tile
static constexpr int COLB = 128;                // CTA col tile
static constexpr int NRB  = (Nc + ROWB - 1) / ROWB;   // 188
static constexpr int NPAD = NRB * ROWB;         // 24064
static constexpr int NCB  = Kc / COLB;          // 32
static constexpr int NKCH = 8;                  // 512 / 64
static constexpr int NCHUNKS = 75;
static constexpr int RCHUNK  = Nc / NCHUNKS;    // 320
static constexpr int STAGE = 32768;             // A 16KB + B 16KB per stage
static constexpr int SMEM_BYTES = 3 * STAGE;    // 98304

// ---------------- device scratch ----------------
__device__ __nv_bfloat16 g_w[(size_t)NPAD * Kc];     // exp(-dist) numerators, ~197MB
__device__ __nv_bfloat16 g_zt[(size_t)NPAD * Dc];    // -2*z bf16, row-major [N][512]
__device__ __nv_bfloat16 g_cbt[(size_t)Kc * Dc];     // bf16 codebook [K][512]
__device__ float g_Z[Nc];
__device__ float g_invZ[Nc];
__device__ float g_z2[Nc];
__device__ float g_c2[Kc];
__device__ int   g_nvalid[Bc];
__device__ float g_partial[NCHUNKS][Kc];

// ---------------- helpers ----------------
__device__ __forceinline__ uint32_t smem_u32(const void* p) {
    uint32_t a;
    asm("{ .reg .u64 t; cvta.to.shared.u64 t, %1; cvt.u32.u64 %0, t; }" : "=r"(a) : "l"(p));
    return a;
}
__device__ __forceinline__ uint32_t swz(uint32_t off) { return off ^ ((off >> 3) & 0x70); }

#define CP_ASYNC16(dst, src) \
    asm volatile("cp.async.cg.shared.global [%0], [%1], 16;" :: "r"(dst), "l"(src))
#define CP_COMMIT() asm volatile("cp.async.commit_group;")
#define CP_WAIT(n)  asm volatile("cp.async.wait_group %0;" :: "n"(n))

#define LDSM4(R, addr) \
    asm volatile("ldmatrix.sync.aligned.m8n8.x4.shared.b16 {%0,%1,%2,%3}, [%4];" \
        : "=r"((R)[0]), "=r"((R)[1]), "=r"((R)[2]), "=r"((R)[3]) : "r"(addr))

#define MMA_BF16(C, A, b0, b1) \
    asm volatile("mma.sync.aligned.m16n8k16.row.col.f32.bf16.bf16.f32 " \
        "{%0,%1,%2,%3}, {%4,%5,%6,%7}, {%8,%9}, {%0,%1,%2,%3};" \
        : "+f"((C)[0]), "+f"((C)[1]), "+f"((C)[2]), "+f"((C)[3]) \
        : "r"((A)[0]), "r"((A)[1]), "r"((A)[2]), "r"((A)[3]), "r"(b0), "r"(b1))

// ---------------- kernel 0: init ----------------
__global__ void k_init(const void* lenp, const void* stridep) {
    int i = blockIdx.x * blockDim.x + threadIdx.x;
    int total = blockDim.x * gridDim.x;
    for (int n = i; n < Nc; n += total) g_Z[n] = 0.f;
    // zero padding rows of g_zt (rows Nc..NPAD)
    const __nv_bfloat16 zb = __float2bfloat16(0.f);
    for (int j = i; j < (NPAD - Nc) * Dc; j += total) g_zt[(size_t)Nc * Dc + j] = zb;
    if (i == 0) {
        long long s = 320;
        if (stridep) {
            long long v = *(const long long*)stridep;
            if (v > 0 && v < (1ll << 31)) s = v;
            else { int v32 = *(const int*)stridep; if (v32 > 0) s = v32; }
        }
        const long long* l64 = (const long long*)lenp;
        const int*       l32 = (const int*)lenp;
        bool is64 = true;
        for (int b = 0; b < Bc; b++) {
            long long v = l64[b];
            if (v < 0 || v >= (1ll << 31)) { is64 = false; break; }
        }
        for (int b = 0; b < Bc; b++) {
            long long L = is64 ? l64[b] : (long long)l32[b];
            long long nv = L / s;
            if (nv > Tc) nv = Tc;
            if (nv < 0) nv = 0;
            g_nvalid[b] = (int)nv;
        }
    }
}

// ---------------- transpose feat -> g_zt = bf16(-2*z), [N][512] ----------------
__global__ void k_prep(const float* __restrict__ feat) {
    __shared__ float tile[32][33];
    int b  = blockIdx.z;
    int d0 = blockIdx.y * 32;
    int t0 = blockIdx.x * 32;
    int tx = threadIdx.x & 31;
    int ty = threadIdx.x >> 5;
    const float* src = feat + (size_t)b * Dc * Tc;
    #pragma unroll
    for (int j = 0; j < 4; j++) {
        int d = d0 + ty + j * 8, t = t0 + tx;
        tile[ty + j * 8][tx] = (t < Tc) ? src[(size_t)d * Tc + t] : 0.f;
    }
    __syncthreads();
    #pragma unroll
    for (int j = 0; j < 4; j++) {
        int t = t0 + ty + j * 8, d = d0 + tx;
        if (t < Tc)
            g_zt[(size_t)(b * Tc + t) * Dc + d] = __float2bfloat16(-2.f * tile[tx][ty + j * 8]);
    }
}

// ---------------- z2 ----------------
__global__ void k_z2(const float* __restrict__ feat) {
    int n = blockIdx.x * blockDim.x + threadIdx.x;
    if (n >= Nc) return;
    int b = n / Tc, t = n - b * Tc;
    const float* p = feat + (size_t)b * Dc * Tc + t;
    float s0 = 0.f, s1 = 0.f, s2 = 0.f, s3 = 0.f;
    #pragma unroll 4
    for (int d = 0; d < Dc; d += 4) {
        float v0 = p[(size_t)(d + 0) * Tc], v1 = p[(size_t)(d + 1) * Tc];
        float v2 = p[(size_t)(d + 2) * Tc], v3 = p[(size_t)(d + 3) * Tc];
        s0 += v0 * v0; s1 += v1 * v1; s2 += v2 * v2; s3 += v3 * v3;
    }
    g_z2[n] = (s0 + s1) + (s2 + s3);
}

// ---------------- c2 + bf16 codebook copy ----------------
__global__ void k_c2(const float* __restrict__ cb) {
    int warp = (blockIdx.x * blockDim.x + threadIdx.x) >> 5;
    int lane = threadIdx.x & 31;
    if (warp >= Kc) return;
    const float* r = cb + (size_t)warp * Dc;
    __nv_bfloat16* w = g_cbt + (size_t)warp * Dc;
    float s = 0.f;
    for (int d = lane; d < Dc; d += 32) {
        float v = r[d];
        s += v * v;
        w[d] = __float2bfloat16(v);
    }
    #pragma unroll
    for (int o = 16; o; o >>= 1) s += __shfl_down_sync(0xffffffffu, s, o);
    if (lane == 0) g_c2[warp] = s;
}

// ---------------- cp.async stage issue ----------------
__device__ __forceinline__ void issue_stage(uint32_t sb, int kc, int n0, int k0, int tid) {
    uint32_t sbase = sb + (uint32_t)(kc % 3) * STAGE;
    int kcol = kc * 64;
    #pragma unroll
    for (int i = 0; i < 4; i++) {
        int id = i * 256 + tid;
        int row = id >> 3, ch = id & 7;
        const void* src = &g_zt[(size_t)(n0 + row) * Dc + kcol + ch * 8];
        uint32_t dst = sbase + swz((uint32_t)(row * 128 + ch * 16));
        CP_ASYNC16(dst, src);
    }
    #pragma unroll
    for (int i = 0; i < 4; i++) {
        int id = i * 256 + tid;
        int row = id >> 3, ch = id & 7;
        const void* src = &g_cbt[(size_t)(k0 + row) * Dc + kcol + ch * 8];
        uint32_t dst = sbase + 16384u + swz((uint32_t)(row * 128 + ch * 16));
        CP_ASYNC16(dst, src);
    }
    CP_COMMIT();
}

// ---------------- bf16 mma GEMM + fused softmax-numerator epilogue ----------------
// CTA 128x128, 8 warps in 2x4. Warp tile 64x32 = 4 m-tiles(16) x 4 n-tiles(8).
__global__ __launch_bounds__(256, 2)
void k_gemm_mma() {
    extern __shared__ __align__(1024) char smem[];
    const uint32_t sb = smem_u32(smem);
    const int tid  = threadIdx.x;
    const int warp = tid >> 5;
    const int lane = tid & 31;
    const int k0 = blockIdx.x * COLB;
    const int n0 = blockIdx.y * ROWB;

    // skip CTA if all 128 rows masked
    __shared__ int s_any;
    if (tid == 0) s_any = 0;
    __syncthreads();
    if (tid < 128) {
        int n = n0 + tid;
        if (n < Nc) {
            int b = n / Tc, t = n - b * Tc;
            if (t < g_nvalid[b]) s_any = 1;
        }
    }
    __syncthreads();
    if (!s_any) return;

    issue_stage(sb, 0, n0, k0, tid);
    issue_stage(sb, 1, n0, k0, tid);

    const int wr = warp >> 2;      // 0..1
    const int wc = warp & 3;       // 0..3
    const int g  = lane >> 3;      // 0..3 (ldmatrix address group)
    const int lr = lane & 7;

    uint32_t aoff[4], boff[2];
    {
        int arow  = wr * 64 + (g & 1) * 8 + lr;
        int acolb = (g >> 1) * 16;
        #pragma unroll
        for (int mt = 0; mt < 4; mt++)
            aoff[mt] = swz((uint32_t)((arow + mt * 16) * 128 + acolb));
        int bcolb = (g & 1) * 16;
        #pragma unroll
        for (int p = 0; p < 2; p++) {
            int brow = wc * 32 + p * 16 + (g >> 1) * 8 + lr;
            boff[p] = 16384u + swz((uint32_t)(brow * 128 + bcolb));
        }
    }

    float acc[4][4][4];
    #pragma unroll
    for (int mt = 0; mt < 4; mt++)
        #pragma unroll
        for (int nt = 0; nt < 4; nt++)
            #pragma unroll
            for (int q = 0; q < 4; q++) acc[mt][nt][q] = 0.f;

    #pragma unroll 1
    for (int kc = 0; kc < NKCH; kc++) {
        if (kc < NKCH - 1) { CP_WAIT(1); } else { CP_WAIT(0); }
        __syncthreads();
        if (kc + 2 < NKCH) issue_stage(sb, kc + 2, n0, k0, tid);
        uint32_t sbase = sb + (uint32_t)(kc % 3) * STAGE;
        #pragma unroll
        for (int ks = 0; ks < 4; ks++) {
            // NOTE: k-step advance must be XORed into the swizzled address.
            // swz(off + ks*32) == swz(off) ^ (ks*32) because the pre-swizzle
            // column bit (bit 4) and ks bits (5-6) are disjoint and the XOR
            // term depends only on bits 7-9. Adding instead of XORing can
            // carry into bit 7 (row index) -> wrong data + smem OOB.
            const uint32_t kx = (uint32_t)(ks * 32);
            uint32_t A[4][4], B[2][4];
            #pragma unroll
            for (int mt = 0; mt < 4; mt++) LDSM4(A[mt], sbase + (aoff[mt] ^ kx));
            #pragma unroll
            for (int p = 0; p < 2; p++)    LDSM4(B[p],  sbase + (boff[p] ^ kx));
            #pragma unroll
            for (int mt = 0; mt < 4; mt++)
                #pragma unroll
                for (int nt = 0; nt < 4; nt++)
                    MMA_BF16(acc[mt][nt], A[mt], B[nt >> 1][(nt & 1) * 2], B[nt >> 1][(nt & 1) * 2 + 1]);
        }
    }

    // ---- fused epilogue: w = exp(-sqrt(max(z2 + c2 + acc, 1e-12))) ----
    const float NLOG2E = -1.4426950408889634f;
    const int rowq = lane >> 2;           // 0..7
    const int colp = (lane & 3) * 2;
    #pragma unroll
    for (int mt = 0; mt < 4; mt++) {
        int r0 = n0 + wr * 64 + mt * 16 + rowq;
        int r1 = r0 + 8;
        int b0i = r0 / Tc, t0i = r0 - b0i * Tc;
        int b1i = r1 / Tc, t1i = r1 - b1i * Tc;
        bool v0 = (r0 < Nc) && (t0i < g_nvalid[b0i]);
        bool v1 = (r1 < Nc) && (t1i < g_nvalid[b1i]);
        float z20 = v0 ? g_z2[r0] : 0.f;
        float z21 = v1 ? g_z2[r1] : 0.f;
        float rs0 = 0.f, rs1 = 0.f;
        #pragma unroll
        for (int nt = 0; nt < 4; nt++) {
            int col = k0 + wc * 32 + nt * 8 + colp;
            float2 c2 = *(const float2*)&g_c2[col];
            if (v0) {
                float d2a = fmaxf(z20 + c2.x + acc[mt][nt][0], 1e-12f);
                float d2b = fmaxf(z20 + c2.y + acc[mt][nt][1], 1e-12f);
                float w0 = exp2f(NLOG2E * (d2a * rsqrtf(d2a)));
                float w1 = exp2f(NLOG2E * (d2b * rsqrtf(d2b)));
                rs0 += w0 + w1;
                __nv_bfloat162 pk = __floats2bfloat162_rn(w0, w1);
                *(__nv_bfloat162*)&g_w[(size_t)r0 * Kc + col] = pk;
            }
            if (v1) {
                float d2a = fmaxf(z21 + c2.x + acc[mt][nt][2], 1e-12f);
                float d2b = fmaxf(z21 + c2.y + acc[mt][nt][3], 1e-12f);
                float w0 = exp2f(NLOG2E * (d2a * rsqrtf(d2a)));
                float w1 = exp2f(NLOG2E * (d2b * rsqrtf(d2b)));
                rs1 += w0 + w1;
                __nv_bfloat162 pk = __floats2bfloat162_rn(w0, w1);
                *(__nv_bfloat162*)&g_w[(size_t)r1 * Kc + col] = pk;
            }
        }
        rs0 += __shfl_xor_sync(0xffffffffu, rs0, 1);
        rs0 += __shfl_xor_sync(0xffffffffu, rs0, 2);
        rs1 += __shfl_xor_sync(0xffffffffu, rs1, 1);
        rs1 += __shfl_xor_sync(0xffffffffu, rs1, 2);
        if ((lane & 3) == 0) {
            if (v0) atomicAdd(&g_Z[r0], rs0);
            if (v1) atomicAdd(&g_Z[r1], rs1);
        }
    }
}

// ---------------- invZ ----------------
__global__ void k_invz() {
    int n = blockIdx.x * blockDim.x + threadIdx.x;
    if (n >= Nc) return;
    float Z = g_Z[n];
    g_invZ[n] = (Z > 0.f) ? (1.f / Z) : 0.f;
}

// ---------------- column reduce ----------------
__global__ void k_colreduce() {
    int k = blockIdx.x * blockDim.x + threadIdx.x;
    int n = blockIdx.y * RCHUNK;
    int b = n / Tc, t = n - b * Tc;
    int nv = g_nvalid[b];
    float acc = 0.f;
    for (int i = 0; i < RCHUNK; i++, n++, t++) {
        if (t >= Tc) { t = 0; b++; nv = g_nvalid[b]; }
        if (t < nv) {
            float w = __bfloat162float(g_w[(size_t)n * Kc + k]);
            acc += w * g_invZ[n];
        }
    }
    g_partial[blockIdx.y][k] = acc;
}

// ---------------- final entropy ----------------
__device__ __forceinline__ float blockSum(float v) {
    __shared__ float sh[32];
    int lane = threadIdx.x & 31, w = threadIdx.x >> 5;
    #pragma unroll
    for (int o = 16; o; o >>= 1) v += __shfl_down_sync(0xffffffffu, v, o);
    if (!lane) sh[w] = v;
    __syncthreads();
    float r = 0.f;
    if (w == 0) {
        r = (lane < (blockDim.x >> 5)) ? sh[lane] : 0.f;
        #pragma unroll
        for (int o = 16; o; o >>= 1) r += __shfl_down_sync(0xffffffffu, r, o);
        if (!lane) sh[0] = r;
    }
    __syncthreads();
    float out = sh[0];
    __syncthreads();
    return out;
}

__global__ void k_final(float* out) {
    const int tid = threadIdx.x;   // 1024
    float cd[4];
    #pragma unroll
    for (int j = 0; j < 4; j++) {
        int k = tid + j * 1024;
        float s = 0.f;
        for (int c = 0; c < NCHUNKS; c++) s += g_partial[c][k];
        cd[j] = s;
    }
    float tot = (cd[0] + cd[1]) + (cd[2] + cd[3]);
    float S = blockSum(tot);
    float denom = S + 1e-8f;
    float e = 0.f;
    #pragma unroll
    for (int j = 0; j < 4; j++) {
        float p = cd[j] / denom;
        e += p * logf(p + 1e-8f);
    }
    float E = blockSum(e);
    if (tid == 0) out[0] = 1.f + E / logf((float)Kc);
}

// ---------------- launch ----------------
extern "C" void kernel_launch(void* const* d_in, const int* in_sizes, int n_in,
                              void* d_out, int out_size) {
    const float* feat = (const float*)d_in[0];
    const float* cb   = (const float*)d_in[1];
    const void*  lenp = d_in[2];
    const void*  stridep = (n_in > 3) ? d_in[3] : nullptr;

    cudaFuncSetAttribute(k_gemm_mma, cudaFuncAttributeMaxDynamicSharedMemorySize, SMEM_BYTES);

    k_init<<<94, 256>>>(lenp, stridep);
    dim3 gp((Tc + 31) / 32, Dc / 32, Bc);   // 47 x 16 x 16
    k_prep<<<gp, 256>>>(feat);
    k_z2<<<(Nc + 255) / 256, 256>>>(feat);
    k_c2<<<Kc / 8, 256>>>(cb);

    dim3 gg(NCB, NRB);                       // 32 x 188
    k_gemm_mma<<<gg, 256, SMEM_BYTES>>>();

    k_invz<<<(Nc + 255) / 256, 256>>>();
    dim3 gr(Kc / 256, NCHUNKS);
    k_colreduce<<<gr, 256>>>();
    k_final<<<1, 1024>>>((float*)d_out);
    (void)in_sizes; (void)out_size;
}

// round 6
// speedup vs baseline: 4.9759x; 1.2101x over previous
#include <cuda_runtime.h>
#include <cuda_bf16.h>
#include <cstdint>
#include <cstddef>

// ---------------- problem constants ----------------
static constexpr int Bc = 16;
static constexpr int Dc = 512;
static constexpr int Tc = 1500;
static constexpr int Nc = Bc * Tc;              // 24000
static constexpr int Kc = 4096;
static constexpr int ROWB = 128;                // CTA row tile
static constexpr int COLB = 128;                // CTA col tile
static constexpr int NRB  = (Nc + ROWB - 1) / ROWB;   // 188
static constexpr int NPAD = NRB * ROWB;         // 24064
static constexpr int NCB  = Kc / COLB;          // 32
static constexpr int NKCH = 8;                  // 512 / 64
static constexpr int NCHUNKS = 75;
static constexpr int RCHUNK  = Nc / NCHUNKS;    // 320
static constexpr int STAGE = 32768;             // A 16KB + B 16KB per stage
static constexpr int SMEM_BYTES = 2 * STAGE;    // 65536 -> 2 CTAs/SM

// ---------------- device scratch ----------------
__device__ __nv_bfloat16 g_w[(size_t)NPAD * Kc];     // exp(-dist) numerators, ~197MB
__device__ __nv_bfloat16 g_zt[(size_t)NPAD * Dc];    // -2*z bf16, row-major [N][512]
__device__ __nv_bfloat16 g_cbt[(size_t)Kc * Dc];     // bf16 codebook [K][512]
__device__ float g_Z[Nc];
__device__ float g_invZ[Nc];
__device__ float g_z2[Nc];
__device__ float g_c2[Kc];
__device__ int   g_nvalid[Bc];
__device__ float g_partial[NCHUNKS][Kc];

// ---------------- helpers ----------------
__device__ __forceinline__ uint32_t smem_u32(const void* p) {
    uint32_t a;
    asm("{ .reg .u64 t; cvta.to.shared.u64 t, %1; cvt.u32.u64 %0, t; }" : "=r"(a) : "l"(p));
    return a;
}
__device__ __forceinline__ uint32_t swz(uint32_t off) { return off ^ ((off >> 3) & 0x70); }
__device__ __forceinline__ float fsqrt_ap(float x) {
    float r; asm("sqrt.approx.ftz.f32 %0, %1;" : "=f"(r) : "f"(x)); return r;
}
__device__ __forceinline__ float fex2_ap(float x) {
    float r; asm("ex2.approx.ftz.f32 %0, %1;" : "=f"(r) : "f"(x)); return r;
}

#define CP_ASYNC16(dst, src) \
    asm volatile("cp.async.cg.shared.global [%0], [%1], 16;" :: "r"(dst), "l"(src))
#define CP_COMMIT() asm volatile("cp.async.commit_group;")
#define CP_WAIT(n)  asm volatile("cp.async.wait_group %0;" :: "n"(n))

#define LDSM4(R, addr) \
    asm volatile("ldmatrix.sync.aligned.m8n8.x4.shared.b16 {%0,%1,%2,%3}, [%4];" \
        : "=r"((R)[0]), "=r"((R)[1]), "=r"((R)[2]), "=r"((R)[3]) : "r"(addr))

#define MMA_BF16(C, A, b0, b1) \
    asm volatile("mma.sync.aligned.m16n8k16.row.col.f32.bf16.bf16.f32 " \
        "{%0,%1,%2,%3}, {%4,%5,%6,%7}, {%8,%9}, {%0,%1,%2,%3};" \
        : "+f"((C)[0]), "+f"((C)[1]), "+f"((C)[2]), "+f"((C)[3]) \
        : "r"((A)[0]), "r"((A)[1]), "r"((A)[2]), "r"((A)[3]), "r"(b0), "r"(b1))

// ---------------- kernel 0: init ----------------
__global__ void k_init(const void* lenp, const void* stridep) {
    int i = blockIdx.x * blockDim.x + threadIdx.x;
    int total = blockDim.x * gridDim.x;
    for (int n = i; n < Nc; n += total) { g_Z[n] = 0.f; g_z2[n] = 0.f; }
    // zero padding rows of g_zt (rows Nc..NPAD)
    const __nv_bfloat16 zb = __float2bfloat16(0.f);
    for (int j = i; j < (NPAD - Nc) * Dc; j += total) g_zt[(size_t)Nc * Dc + j] = zb;
    if (i == 0) {
        long long s = 320;
        if (stridep) {
            long long v = *(const long long*)stridep;
            if (v > 0 && v < (1ll << 31)) s = v;
            else { int v32 = *(const int*)stridep; if (v32 > 0) s = v32; }
        }
        const long long* l64 = (const long long*)lenp;
        const int*       l32 = (const int*)lenp;
        bool is64 = true;
        for (int b = 0; b < Bc; b++) {
            long long v = l64[b];
            if (v < 0 || v >= (1ll << 31)) { is64 = false; break; }
        }
        for (int b = 0; b < Bc; b++) {
            long long L = is64 ? l64[b] : (long long)l32[b];
            long long nv = L / s;
            if (nv > Tc) nv = Tc;
            if (nv < 0) nv = 0;
            g_nvalid[b] = (int)nv;
        }
    }
}

// ---------------- transpose feat -> g_zt = bf16(-2*z), fused z2 ----------------
__global__ void k_prep(const float* __restrict__ feat) {
    __shared__ float tile[32][33];
    __shared__ float sz[32];
    int b  = blockIdx.z;
    int d0 = blockIdx.y * 32;
    int t0 = blockIdx.x * 32;
    int tx = threadIdx.x & 31;
    int ty = threadIdx.x >> 5;
    if (threadIdx.x < 32) sz[threadIdx.x] = 0.f;
    __syncthreads();
    const float* src = feat + (size_t)b * Dc * Tc;
    float ssq = 0.f;
    #pragma unroll
    for (int j = 0; j < 4; j++) {
        int d = d0 + ty + j * 8, t = t0 + tx;
        float v = (t < Tc) ? src[(size_t)d * Tc + t] : 0.f;
        tile[ty + j * 8][tx] = v;
        ssq += v * v;
    }
    atomicAdd(&sz[tx], ssq);
    __syncthreads();
    #pragma unroll
    for (int j = 0; j < 4; j++) {
        int t = t0 + ty + j * 8, d = d0 + tx;
        if (t < Tc)
            g_zt[(size_t)(b * Tc + t) * Dc + d] = __float2bfloat16(-2.f * tile[tx][ty + j * 8]);
    }
    if (ty == 0) {
        int t = t0 + tx;
        if (t < Tc) atomicAdd(&g_z2[b * Tc + t], sz[tx]);
    }
}

// ---------------- c2 + bf16 codebook copy (float4 vectorized) ----------------
__global__ void k_c2(const float* __restrict__ cb) {
    int warp = (blockIdx.x * blockDim.x + threadIdx.x) >> 5;
    int lane = threadIdx.x & 31;
    if (warp >= Kc) return;
    const float* r = cb + (size_t)warp * Dc;
    __nv_bfloat16* w = g_cbt + (size_t)warp * Dc;
    float s = 0.f;
    #pragma unroll
    for (int it = 0; it < 4; it++) {
        int d = it * 128 + lane * 4;
        float4 v = *(const float4*)(r + d);
        s += v.x * v.x + v.y * v.y + v.z * v.z + v.w * v.w;
        __nv_bfloat162 p0 = __floats2bfloat162_rn(v.x, v.y);
        __nv_bfloat162 p1 = __floats2bfloat162_rn(v.z, v.w);
        uint2 st = make_uint2(*(uint32_t*)&p0, *(uint32_t*)&p1);
        *(uint2*)(w + d) = st;
    }
    #pragma unroll
    for (int o = 16; o; o >>= 1) s += __shfl_down_sync(0xffffffffu, s, o);
    if (lane == 0) g_c2[warp] = s;
}

// ---------------- cp.async stage issue ----------------
__device__ __forceinline__ void issue_stage(uint32_t sb, int kc, int n0, int k0, int tid) {
    uint32_t sbase = sb + (uint32_t)(kc & 1) * STAGE;
    int kcol = kc * 64;
    #pragma unroll
    for (int i = 0; i < 4; i++) {
        int id = i * 256 + tid;
        int row = id >> 3, ch = id & 7;
        const void* src = &g_zt[(size_t)(n0 + row) * Dc + kcol + ch * 8];
        uint32_t dst = sbase + swz((uint32_t)(row * 128 + ch * 16));
        CP_ASYNC16(dst, src);
    }
    #pragma unroll
    for (int i = 0; i < 4; i++) {
        int id = i * 256 + tid;
        int row = id >> 3, ch = id & 7;
        const void* src = &g_cbt[(size_t)(k0 + row) * Dc + kcol + ch * 8];
        uint32_t dst = sbase + 16384u + swz((uint32_t)(row * 128 + ch * 16));
        CP_ASYNC16(dst, src);
    }
    CP_COMMIT();
}

// ---------------- bf16 mma GEMM + fused softmax-numerator epilogue ----------------
// CTA 128x128, 8 warps in 2x4. Warp tile 64x32. 2-stage cp.async -> 2 CTAs/SM.
__global__ __launch_bounds__(256, 2)
void k_gemm_mma() {
    extern __shared__ __align__(1024) char smem[];
    const uint32_t sb = smem_u32(smem);
    const int tid  = threadIdx.x;
    const int warp = tid >> 5;
    const int lane = tid & 31;
    const int k0 = blockIdx.x * COLB;
    const int n0 = blockIdx.y * ROWB;

    // skip CTA if all 128 rows masked
    __shared__ int s_any;
    if (tid == 0) s_any = 0;
    __syncthreads();
    if (tid < 128) {
        int n = n0 + tid;
        if (n < Nc) {
            int b = n / Tc, t = n - b * Tc;
            if (t < g_nvalid[b]) s_any = 1;
        }
    }
    __syncthreads();
    if (!s_any) return;

    issue_stage(sb, 0, n0, k0, tid);
    issue_stage(sb, 1, n0, k0, tid);

    const int wr = warp >> 2;      // 0..1
    const int wc = warp & 3;       // 0..3
    const int g  = lane >> 3;      // 0..3 (ldmatrix address group)
    const int lr = lane & 7;

    uint32_t aoff[4], boff[2];
    {
        int arow  = wr * 64 + (g & 1) * 8 + lr;
        int acolb = (g >> 1) * 16;
        #pragma unroll
        for (int mt = 0; mt < 4; mt++)
            aoff[mt] = swz((uint32_t)((arow + mt * 16) * 128 + acolb));
        int bcolb = (g & 1) * 16;
        #pragma unroll
        for (int p = 0; p < 2; p++) {
            int brow = wc * 32 + p * 16 + (g >> 1) * 8 + lr;
            boff[p] = 16384u + swz((uint32_t)(brow * 128 + bcolb));
        }
    }

    float acc[4][4][4];
    #pragma unroll
    for (int mt = 0; mt < 4; mt++)
        #pragma unroll
        for (int nt = 0; nt < 4; nt++)
            #pragma unroll
            for (int q = 0; q < 4; q++) acc[mt][nt][q] = 0.f;

    #pragma unroll 1
    for (int kc = 0; kc < NKCH; kc++) {
        if (kc < NKCH - 1) { CP_WAIT(1); } else { CP_WAIT(0); }
        __syncthreads();
        uint32_t sbase = sb + (uint32_t)(kc & 1) * STAGE;
        #pragma unroll
        for (int ks = 0; ks < 4; ks++) {
            // k-step advance XORed into swizzled address (carry-free):
            // swz(off + ks*32) == swz(off) ^ (ks*32).
            const uint32_t kx = (uint32_t)(ks * 32);
            uint32_t A[4][4], B[2][4];
            #pragma unroll
            for (int mt = 0; mt < 4; mt++) LDSM4(A[mt], sbase + (aoff[mt] ^ kx));
            #pragma unroll
            for (int p = 0; p < 2; p++)    LDSM4(B[p],  sbase + (boff[p] ^ kx));
            #pragma unroll
            for (int mt = 0; mt < 4; mt++)
                #pragma unroll
                for (int nt = 0; nt < 4; nt++)
                    MMA_BF16(acc[mt][nt], A[mt], B[nt >> 1][(nt & 1) * 2], B[nt >> 1][(nt & 1) * 2 + 1]);
        }
        if (kc + 2 < NKCH) {
            __syncthreads();                  // all reads of this buffer done
            issue_stage(sb, kc + 2, n0, k0, tid);
        }
    }

    // ---- fused epilogue: w = ex2(-log2e * sqrt(max(z2 + c2 + acc, 1e-12))) ----
    const float NLOG2E = -1.4426950408889634f;
    const int rowq = lane >> 2;           // 0..7
    const int colp = (lane & 3) * 2;
    #pragma unroll
    for (int mt = 0; mt < 4; mt++) {
        int r0 = n0 + wr * 64 + mt * 16 + rowq;
        int r1 = r0 + 8;
        int b0i = r0 / Tc, t0i = r0 - b0i * Tc;
        int b1i = r1 / Tc, t1i = r1 - b1i * Tc;
        bool v0 = (r0 < Nc) && (t0i < g_nvalid[b0i]);
        bool v1 = (r1 < Nc) && (t1i < g_nvalid[b1i]);
        float z20 = v0 ? g_z2[r0] : 0.f;
        float z21 = v1 ? g_z2[r1] : 0.f;
        float rs0 = 0.f, rs1 = 0.f;
        #pragma unroll
        for (int nt = 0; nt < 4; nt++) {
            int col = k0 + wc * 32 + nt * 8 + colp;
            float2 c2 = *(const float2*)&g_c2[col];
            if (v0) {
                float d2a = fmaxf(z20 + c2.x + acc[mt][nt][0], 1e-12f);
                float d2b = fmaxf(z20 + c2.y + acc[mt][nt][1], 1e-12f);
                float w0 = fex2_ap(NLOG2E * fsqrt_ap(d2a));
                float w1 = fex2_ap(NLOG2E * fsqrt_ap(d2b));
                rs0 += w0 + w1;
                __nv_bfloat162 pk = __floats2bfloat162_rn(w0, w1);
                *(__nv_bfloat162*)&g_w[(size_t)r0 * Kc + col] = pk;
            }
            if (v1) {
                float d2a = fmaxf(z21 + c2.x + acc[mt][nt][2], 1e-12f);
                float d2b = fmaxf(z21 + c2.y + acc[mt][nt][3], 1e-12f);
                float w0 = fex2_ap(NLOG2E * fsqrt_ap(d2a));
                float w1 = fex2_ap(NLOG2E * fsqrt_ap(d2b));
                rs1 += w0 + w1;
                __nv_bfloat162 pk = __floats2bfloat162_rn(w0, w1);
                *(__nv_bfloat162*)&g_w[(size_t)r1 * Kc + col] = pk;
            }
        }
        rs0 += __shfl_xor_sync(0xffffffffu, rs0, 1);
        rs0 += __shfl_xor_sync(0xffffffffu, rs0, 2);
        rs1 += __shfl_xor_sync(0xffffffffu, rs1, 1);
        rs1 += __shfl_xor_sync(0xffffffffu, rs1, 2);
        if ((lane & 3) == 0) {
            if (v0) atomicAdd(&g_Z[r0], rs0);
            if (v1) atomicAdd(&g_Z[r1], rs1);
        }
    }
}

// ---------------- invZ ----------------
__global__ void k_invz() {
    int n = blockIdx.x * blockDim.x + threadIdx.x;
    if (n >= Nc) return;
    float Z = g_Z[n];
    g_invZ[n] = (Z > 0.f) ? (1.f / Z) : 0.f;
}

// ---------------- column reduce (bf16x2 vectorized) ----------------
__global__ void k_colreduce() {
    int k2 = blockIdx.x * blockDim.x + threadIdx.x;   // 0..2047 (pairs)
    int n = blockIdx.y * RCHUNK;
    int b = n / Tc, t = n - b * Tc;
    int nv = g_nvalid[b];
    float ax = 0.f, ay = 0.f;
    for (int i = 0; i < RCHUNK; i++, n++, t++) {
        if (t >= Tc) { t = 0; b++; nv = g_nvalid[b]; }
        if (t < nv) {
            __nv_bfloat162 w2 = ((const __nv_bfloat162*)&g_w[(size_t)n * Kc])[k2];
            float2 f = __bfloat1622float2(w2);
            float iz = g_invZ[n];
            ax += f.x * iz;
            ay += f.y * iz;
        }
    }
    g_partial[blockIdx.y][k2 * 2]     = ax;
    g_partial[blockIdx.y][k2 * 2 + 1] = ay;
}

// ---------------- final entropy ----------------
__device__ __forceinline__ float blockSum(float v) {
    __shared__ float sh[32];
    int lane = threadIdx.x & 31, w = threadIdx.x >> 5;
    #pragma unroll
    for (int o = 16; o; o >>= 1) v += __shfl_down_sync(0xffffffffu, v, o);
    if (!lane) sh[w] = v;
    __syncthreads();
    float r = 0.f;
    if (w == 0) {
        r = (lane < (blockDim.x >> 5)) ? sh[lane] : 0.f;
        #pragma unroll
        for (int o = 16; o; o >>= 1) r += __shfl_down_sync(0xffffffffu, r, o);
        if (!lane) sh[0] = r;
    }
    __syncthreads();
    float out = sh[0];
    __syncthreads();
    return out;
}

__global__ void k_final(float* out) {
    const int tid = threadIdx.x;   // 1024
    float cd[4];
    #pragma unroll
    for (int j = 0; j < 4; j++) {
        int k = tid + j * 1024;
        float s = 0.f;
        for (int c = 0; c < NCHUNKS; c++) s += g_partial[c][k];
        cd[j] = s;
    }
    float tot = (cd[0] + cd[1]) + (cd[2] + cd[3]);
    float S = blockSum(tot);
    float denom = S + 1e-8f;
    float e = 0.f;
    #pragma unroll
    for (int j = 0; j < 4; j++) {
        float p = cd[j] / denom;
        e += p * logf(p + 1e-8f);
    }
    float E = blockSum(e);
    if (tid == 0) out[0] = 1.f + E / logf((float)Kc);
}

// ---------------- launch ----------------
extern "C" void kernel_launch(void* const* d_in, const int* in_sizes, int n_in,
                              void* d_out, int out_size) {
    const float* feat = (const float*)d_in[0];
    const float* cb   = (const float*)d_in[1];
    const void*  lenp = d_in[2];
    const void*  stridep = (n_in > 3) ? d_in[3] : nullptr;

    cudaFuncSetAttribute(k_gemm_mma, cudaFuncAttributeMaxDynamicSharedMemorySize, SMEM_BYTES);

    k_init<<<94, 256>>>(lenp, stridep);
    dim3 gp((Tc + 31) / 32, Dc / 32, Bc);   // 47 x 16 x 16
    k_prep<<<gp, 256>>>(feat);
    k_c2<<<Kc / 8, 256>>>(cb);

    dim3 gg(NCB, NRB);                       // 32 x 188
    k_gemm_mma<<<gg, 256, SMEM_BYTES>>>();

    k_invz<<<(Nc + 255) / 256, 256>>>();
    dim3 gr(Kc / 512, NCHUNKS);              // 8 x 75 (bf16x2 pairs)
    k_colreduce<<<gr, 256>>>();
    k_final<<<1, 1024>>>((float*)d_out);
    (void)in_sizes; (void)out_size;
}

// round 7
// speedup vs baseline: 5.0187x; 1.0086x over previous
#include <cuda_runtime.h>
#include <cuda_bf16.h>
#include <cstdint>
#include <cstddef>

// ---------------- problem constants ----------------
static constexpr int Bc = 16;
static constexpr int Dc = 512;
static constexpr int Tc = 1500;
static constexpr int Nc = Bc * Tc;              // 24000
static constexpr int Kc = 4096;
static constexpr int ROWB = 128;                // CTA row tile
static constexpr int COLB = 128;                // CTA col tile
static constexpr int NRB  = (Nc + ROWB - 1) / ROWB;   // 188
static constexpr int NPAD = NRB * ROWB;         // 24064
static constexpr int NCB  = Kc / COLB;          // 32
static constexpr int NKCH = 8;                  // 512 / 64
static constexpr int NCHUNKS = 75;
static constexpr int RCHUNK  = Nc / NCHUNKS;    // 320
static constexpr int STAGE = 32768;             // A 16KB + B 16KB per stage
static constexpr int SMEM_BYTES = 2 * STAGE;    // 65536 -> 2 CTAs/SM

// ---------------- device scratch ----------------
__device__ __nv_bfloat16 g_w[(size_t)NPAD * Kc];     // exp(-dist) numerators, ~197MB
__device__ __nv_bfloat16 g_zt[(size_t)NPAD * Dc];    // -2*z bf16, row-major [N][512]
__device__ __nv_bfloat16 g_cbt[(size_t)Kc * Dc];     // bf16 codebook [K][512]
__device__ float g_Z[Nc];
__device__ float g_invZ[Nc];
__device__ float g_z2[Nc];
__device__ float g_c2[Kc];
__device__ int   g_nvalid[Bc];
__device__ float g_partial[NCHUNKS][Kc];
__device__ float g_cd[Kc];

// ---------------- helpers ----------------
__device__ __forceinline__ uint32_t smem_u32(const void* p) {
    uint32_t a;
    asm("{ .reg .u64 t; cvta.to.shared.u64 t, %1; cvt.u32.u64 %0, t; }" : "=r"(a) : "l"(p));
    return a;
}
__device__ __forceinline__ uint32_t swz(uint32_t off) { return off ^ ((off >> 3) & 0x70); }
__device__ __forceinline__ float fsqrt_ap(float x) {
    float r; asm("sqrt.approx.ftz.f32 %0, %1;" : "=f"(r) : "f"(x)); return r;
}
__device__ __forceinline__ float fex2_ap(float x) {
    float r; asm("ex2.approx.ftz.f32 %0, %1;" : "=f"(r) : "f"(x)); return r;
}

#define CP_ASYNC16(dst, src) \
    asm volatile("cp.async.cg.shared.global [%0], [%1], 16;" :: "r"(dst), "l"(src))
#define CP_COMMIT() asm volatile("cp.async.commit_group;")
#define CP_WAIT(n)  asm volatile("cp.async.wait_group %0;" :: "n"(n))

#define LDSM4(R, addr) \
    asm volatile("ldmatrix.sync.aligned.m8n8.x4.shared.b16 {%0,%1,%2,%3}, [%4];" \
        : "=r"((R)[0]), "=r"((R)[1]), "=r"((R)[2]), "=r"((R)[3]) : "r"(addr))

#define MMA_BF16(C, A, b0, b1) \
    asm volatile("mma.sync.aligned.m16n8k16.row.col.f32.bf16.bf16.f32 " \
        "{%0,%1,%2,%3}, {%4,%5,%6,%7}, {%8,%9}, {%0,%1,%2,%3};" \
        : "+f"((C)[0]), "+f"((C)[1]), "+f"((C)[2]), "+f"((C)[3]) \
        : "r"((A)[0]), "r"((A)[1]), "r"((A)[2]), "r"((A)[3]), "r"(b0), "r"(b1))

// ---------------- kernel 0: init ----------------
__global__ void k_init(const void* lenp, const void* stridep) {
    int i = blockIdx.x * blockDim.x + threadIdx.x;
    int total = blockDim.x * gridDim.x;
    for (int n = i; n < Nc; n += total) { g_Z[n] = 0.f; g_z2[n] = 0.f; }
    const __nv_bfloat16 zb = __float2bfloat16(0.f);
    for (int j = i; j < (NPAD - Nc) * Dc; j += total) g_zt[(size_t)Nc * Dc + j] = zb;
    if (i == 0) {
        long long s = 320;
        if (stridep) {
            long long v = *(const long long*)stridep;
            if (v > 0 && v < (1ll << 31)) s = v;
            else { int v32 = *(const int*)stridep; if (v32 > 0) s = v32; }
        }
        const long long* l64 = (const long long*)lenp;
        const int*       l32 = (const int*)lenp;
        bool is64 = true;
        for (int b = 0; b < Bc; b++) {
            long long v = l64[b];
            if (v < 0 || v >= (1ll << 31)) { is64 = false; break; }
        }
        for (int b = 0; b < Bc; b++) {
            long long L = is64 ? l64[b] : (long long)l32[b];
            long long nv = L / s;
            if (nv > Tc) nv = Tc;
            if (nv < 0) nv = 0;
            g_nvalid[b] = (int)nv;
        }
    }
}

// ---------------- transpose feat -> g_zt = bf16(-2*z), fused z2 ----------------
__global__ void k_prep(const float* __restrict__ feat) {
    __shared__ float tile[32][33];
    __shared__ float sz[32];
    int b  = blockIdx.z;
    int d0 = blockIdx.y * 32;
    int t0 = blockIdx.x * 32;
    int tx = threadIdx.x & 31;
    int ty = threadIdx.x >> 5;
    if (threadIdx.x < 32) sz[threadIdx.x] = 0.f;
    __syncthreads();
    const float* src = feat + (size_t)b * Dc * Tc;
    float ssq = 0.f;
    #pragma unroll
    for (int j = 0; j < 4; j++) {
        int d = d0 + ty + j * 8, t = t0 + tx;
        float v = (t < Tc) ? src[(size_t)d * Tc + t] : 0.f;
        tile[ty + j * 8][tx] = v;
        ssq += v * v;
    }
    atomicAdd(&sz[tx], ssq);
    __syncthreads();
    #pragma unroll
    for (int j = 0; j < 4; j++) {
        int t = t0 + ty + j * 8, d = d0 + tx;
        if (t < Tc)
            g_zt[(size_t)(b * Tc + t) * Dc + d] = __float2bfloat16(-2.f * tile[tx][ty + j * 8]);
    }
    if (ty == 0) {
        int t = t0 + tx;
        if (t < Tc) atomicAdd(&g_z2[b * Tc + t], sz[tx]);
    }
}

// ---------------- c2 + bf16 codebook copy (float4 vectorized) ----------------
__global__ void k_c2(const float* __restrict__ cb) {
    int warp = (blockIdx.x * blockDim.x + threadIdx.x) >> 5;
    int lane = threadIdx.x & 31;
    if (warp >= Kc) return;
    const float* r = cb + (size_t)warp * Dc;
    __nv_bfloat16* w = g_cbt + (size_t)warp * Dc;
    float s = 0.f;
    #pragma unroll
    for (int it = 0; it < 4; it++) {
        int d = it * 128 + lane * 4;
        float4 v = *(const float4*)(r + d);
        s += v.x * v.x + v.y * v.y + v.z * v.z + v.w * v.w;
        __nv_bfloat162 p0 = __floats2bfloat162_rn(v.x, v.y);
        __nv_bfloat162 p1 = __floats2bfloat162_rn(v.z, v.w);
        uint2 st = make_uint2(*(uint32_t*)&p0, *(uint32_t*)&p1);
        *(uint2*)(w + d) = st;
    }
    #pragma unroll
    for (int o = 16; o; o >>= 1) s += __shfl_down_sync(0xffffffffu, s, o);
    if (lane == 0) g_c2[warp] = s;
}

// ---------------- cp.async stage issue ----------------
__device__ __forceinline__ void issue_stage(uint32_t sb, int kc, int n0, int k0, int tid) {
    uint32_t sbase = sb + (uint32_t)(kc & 1) * STAGE;
    int kcol = kc * 64;
    #pragma unroll
    for (int i = 0; i < 4; i++) {
        int id = i * 256 + tid;
        int row = id >> 3, ch = id & 7;
        const void* src = &g_zt[(size_t)(n0 + row) * Dc + kcol + ch * 8];
        uint32_t dst = sbase + swz((uint32_t)(row * 128 + ch * 16));
        CP_ASYNC16(dst, src);
    }
    #pragma unroll
    for (int i = 0; i < 4; i++) {
        int id = i * 256 + tid;
        int row = id >> 3, ch = id & 7;
        const void* src = &g_cbt[(size_t)(k0 + row) * Dc + kcol + ch * 8];
        uint32_t dst = sbase + 16384u + swz((uint32_t)(row * 128 + ch * 16));
        CP_ASYNC16(dst, src);
    }
    CP_COMMIT();
}

// ---------------- bf16 mma GEMM + fused softmax-numerator epilogue ----------------
// CTA 128x128, 8 warps in 2x4. Warp tile 64x32. 2-stage cp.async -> 2 CTAs/SM.
__global__ __launch_bounds__(256, 2)
void k_gemm_mma() {
    extern __shared__ __align__(1024) char smem[];
    const uint32_t sb = smem_u32(smem);
    const int tid  = threadIdx.x;
    const int warp = tid >> 5;
    const int lane = tid & 31;
    const int k0 = blockIdx.x * COLB;
    const int n0 = blockIdx.y * ROWB;

    // skip CTA if all 128 rows masked
    __shared__ int s_any;
    if (tid == 0) s_any = 0;
    __syncthreads();
    if (tid < 128) {
        int n = n0 + tid;
        if (n < Nc) {
            int b = n / Tc, t = n - b * Tc;
            if (t < g_nvalid[b]) s_any = 1;
        }
    }
    __syncthreads();
    if (!s_any) return;

    issue_stage(sb, 0, n0, k0, tid);
    issue_stage(sb, 1, n0, k0, tid);

    const int wr = warp >> 2;      // 0..1
    const int wc = warp & 3;       // 0..3
    const int g  = lane >> 3;      // 0..3 (ldmatrix address group)
    const int lr = lane & 7;

    uint32_t aoff[4], boff[2];
    {
        int arow  = wr * 64 + (g & 1) * 8 + lr;
        int acolb = (g >> 1) * 16;
        #pragma unroll
        for (int mt = 0; mt < 4; mt++)
            aoff[mt] = swz((uint32_t)((arow + mt * 16) * 128 + acolb));
        int bcolb = (g & 1) * 16;
        #pragma unroll
        for (int p = 0; p < 2; p++) {
            int brow = wc * 32 + p * 16 + (g >> 1) * 8 + lr;
            boff[p] = 16384u + swz((uint32_t)(brow * 128 + bcolb));
        }
    }

    float acc[4][4][4];
    #pragma unroll
    for (int mt = 0; mt < 4; mt++)
        #pragma unroll
        for (int nt = 0; nt < 4; nt++)
            #pragma unroll
            for (int q = 0; q < 4; q++) acc[mt][nt][q] = 0.f;

    #pragma unroll 1
    for (int kc = 0; kc < NKCH; kc++) {
        if (kc < NKCH - 1) { CP_WAIT(1); } else { CP_WAIT(0); }
        __syncthreads();
        uint32_t sbase = sb + (uint32_t)(kc & 1) * STAGE;
        #pragma unroll
        for (int ks = 0; ks < 4; ks++) {
            // k-step advance XORed into swizzled address (carry-free):
            // swz(off + ks*32) == swz(off) ^ (ks*32).
            const uint32_t kx = (uint32_t)(ks * 32);
            uint32_t A[4][4], B[2][4];
            #pragma unroll
            for (int mt = 0; mt < 4; mt++) LDSM4(A[mt], sbase + (aoff[mt] ^ kx));
            #pragma unroll
            for (int p = 0; p < 2; p++)    LDSM4(B[p],  sbase + (boff[p] ^ kx));
            #pragma unroll
            for (int mt = 0; mt < 4; mt++)
                #pragma unroll
                for (int nt = 0; nt < 4; nt++)
                    MMA_BF16(acc[mt][nt], A[mt], B[nt >> 1][(nt & 1) * 2], B[nt >> 1][(nt & 1) * 2 + 1]);
        }
        if (kc + 2 < NKCH) {
            __syncthreads();                  // all reads of this buffer done
            issue_stage(sb, kc + 2, n0, k0, tid);
        }
    }

    // ---- fused epilogue: w = ex2(-log2e * sqrt(max(z2 + c2 + acc, 1e-12))) ----
    const float NLOG2E = -1.4426950408889634f;
    const int rowq = lane >> 2;           // 0..7
    const int colp = (lane & 3) * 2;
    #pragma unroll
    for (int mt = 0; mt < 4; mt++) {
        int r0 = n0 + wr * 64 + mt * 16 + rowq;
        int r1 = r0 + 8;
        int b0i = r0 / Tc, t0i = r0 - b0i * Tc;
        int b1i = r1 / Tc, t1i = r1 - b1i * Tc;
        bool v0 = (r0 < Nc) && (t0i < g_nvalid[b0i]);
        bool v1 = (r1 < Nc) && (t1i < g_nvalid[b1i]);
        float z20 = v0 ? g_z2[r0] : 0.f;
        float z21 = v1 ? g_z2[r1] : 0.f;
        float rs0 = 0.f, rs1 = 0.f;
        #pragma unroll
        for (int nt = 0; nt < 4; nt++) {
            int col = k0 + wc * 32 + nt * 8 + colp;
            float2 c2 = *(const float2*)&g_c2[col];
            if (v0) {
                float d2a = fmaxf(z20 + c2.x + acc[mt][nt][0], 1e-12f);
                float d2b = fmaxf(z20 + c2.y + acc[mt][nt][1], 1e-12f);
                float w0 = fex2_ap(NLOG2E * fsqrt_ap(d2a));
                float w1 = fex2_ap(NLOG2E * fsqrt_ap(d2b));
                rs0 += w0 + w1;
                __nv_bfloat162 pk = __floats2bfloat162_rn(w0, w1);
                *(__nv_bfloat162*)&g_w[(size_t)r0 * Kc + col] = pk;
            }
            if (v1) {
                float d2a = fmaxf(z21 + c2.x + acc[mt][nt][2], 1e-12f);
                float d2b = fmaxf(z21 + c2.y + acc[mt][nt][3], 1e-12f);
                float w0 = fex2_ap(NLOG2E * fsqrt_ap(d2a));
                float w1 = fex2_ap(NLOG2E * fsqrt_ap(d2b));
                rs1 += w0 + w1;
                __nv_bfloat162 pk = __floats2bfloat162_rn(w0, w1);
                *(__nv_bfloat162*)&g_w[(size_t)r1 * Kc + col] = pk;
            }
        }
        rs0 += __shfl_xor_sync(0xffffffffu, rs0, 1);
        rs0 += __shfl_xor_sync(0xffffffffu, rs0, 2);
        rs1 += __shfl_xor_sync(0xffffffffu, rs1, 1);
        rs1 += __shfl_xor_sync(0xffffffffu, rs1, 2);
        if ((lane & 3) == 0) {
            if (v0) atomicAdd(&g_Z[r0], rs0);
            if (v1) atomicAdd(&g_Z[r1], rs1);
        }
    }
}

// ---------------- invZ ----------------
__global__ void k_invz() {
    int n = blockIdx.x * blockDim.x + threadIdx.x;
    if (n >= Nc) return;
    float Z = g_Z[n];
    g_invZ[n] = (Z > 0.f) ? (1.f / Z) : 0.f;
}

// ---------------- column reduce (bf16x2 vectorized) ----------------
__global__ void k_colreduce() {
    int k2 = blockIdx.x * blockDim.x + threadIdx.x;   // 0..2047 (pairs)
    int n = blockIdx.y * RCHUNK;
    int b = n / Tc, t = n - b * Tc;
    int nv = g_nvalid[b];
    float ax = 0.f, ay = 0.f;
    #pragma unroll 4
    for (int i = 0; i < RCHUNK; i++, n++, t++) {
        if (t >= Tc) { t = 0; b++; nv = g_nvalid[b]; }
        if (t < nv) {
            __nv_bfloat162 w2 = ((const __nv_bfloat162*)&g_w[(size_t)n * Kc])[k2];
            float2 f = __bfloat1622float2(w2);
            float iz = g_invZ[n];
            ax += f.x * iz;
            ay += f.y * iz;
        }
    }
    g_partial[blockIdx.y][k2 * 2]     = ax;
    g_partial[blockIdx.y][k2 * 2 + 1] = ay;
}

// ---------------- parallel chunk reduction: cd[k] = sum_c partial[c][k] ----------------
__global__ void k_reduce_cd() {
    int k = blockIdx.x * blockDim.x + threadIdx.x;   // 4096 threads
    float s = 0.f;
    #pragma unroll 5
    for (int c = 0; c < NCHUNKS; c++) s += g_partial[c][k];
    g_cd[k] = s;
}

// ---------------- final entropy (reads only 16KB) ----------------
__device__ __forceinline__ float blockSum(float v) {
    __shared__ float sh[32];
    int lane = threadIdx.x & 31, w = threadIdx.x >> 5;
    #pragma unroll
    for (int o = 16; o; o >>= 1) v += __shfl_down_sync(0xffffffffu, v, o);
    if (!lane) sh[w] = v;
    __syncthreads();
    float r = 0.f;
    if (w == 0) {
        r = (lane < (blockDim.x >> 5)) ? sh[lane] : 0.f;
        #pragma unroll
        for (int o = 16; o; o >>= 1) r += __shfl_down_sync(0xffffffffu, r, o);
        if (!lane) sh[0] = r;
    }
    __syncthreads();
    float out = sh[0];
    __syncthreads();
    return out;
}

__global__ void k_final(float* out) {
    const int tid = threadIdx.x;   // 1024
    float cd[4];
    #pragma unroll
    for (int j = 0; j < 4; j++) cd[j] = g_cd[tid + j * 1024];
    float tot = (cd[0] + cd[1]) + (cd[2] + cd[3]);
    float S = blockSum(tot);
    float denom = S + 1e-8f;
    float e = 0.f;
    #pragma unroll
    for (int j = 0; j < 4; j++) {
        float p = cd[j] / denom;
        e += p * logf(p + 1e-8f);
    }
    float E = blockSum(e);
    if (tid == 0) out[0] = 1.f + E / logf((float)Kc);
}

// ---------------- launch ----------------
extern "C" void kernel_launch(void* const* d_in, const int* in_sizes, int n_in,
                              void* d_out, int out_size) {
    const float* feat = (const float*)d_in[0];
    const float* cb   = (const float*)d_in[1];
    const void*  lenp = d_in[2];
    const void*  stridep = (n_in > 3) ? d_in[3] : nullptr;

    cudaFuncSetAttribute(k_gemm_mma, cudaFuncAttributeMaxDynamicSharedMemorySize, SMEM_BYTES);

    k_init<<<94, 256>>>(lenp, stridep);
    dim3 gp((Tc + 31) / 32, Dc / 32, Bc);   // 47 x 16 x 16
    k_prep<<<gp, 256>>>(feat);
    k_c2<<<Kc / 8, 256>>>(cb);

    dim3 gg(NCB, NRB);                       // 32 x 188
    k_gemm_mma<<<gg, 256, SMEM_BYTES>>>();

    k_invz<<<(Nc + 255) / 256, 256>>>();
    dim3 gr(Kc / 512, NCHUNKS);              // 8 x 75 (bf16x2 pairs)
    k_colreduce<<<gr, 256>>>();
    k_reduce_cd<<<16, 256>>>();
    k_final<<<1, 1024>>>((float*)d_out);
    (void)in_sizes; (void)out_size;
}

// round 8
// speedup vs baseline: 5.5776x; 1.1114x over previous
#include <cuda_runtime.h>
#include <cuda_bf16.h>
#include <cstdint>
#include <cstddef>

// ---------------- problem constants ----------------
static constexpr int Bc = 16;
static constexpr int Dc = 512;
static constexpr int Tc = 1500;
static constexpr int Nc = Bc * Tc;              // 24000
static constexpr int Kc = 4096;
static constexpr int ROWB = 128;                // CTA row tile
static constexpr int COLB = 128;                // CTA col tile
static constexpr int NRB  = (Nc + ROWB - 1) / ROWB;   // 188
static constexpr int NPAD = NRB * ROWB;         // 24064
static constexpr int NCB  = Kc / COLB;          // 32
static constexpr int NKCH = 8;                  // 512 / 64
static constexpr int CPB    = 10;               // chunks per batch
static constexpr int RCHUNK = Tc / CPB;         // 150 rows, batch-aligned
static constexpr int NCHUNKS = Bc * CPB;        // 160
static constexpr int STAGE = 32768;             // A 16KB + B 16KB per stage
static constexpr int SMEM_BYTES = 2 * STAGE;    // 65536 -> 2 CTAs/SM

// ---------------- device scratch ----------------
__device__ __nv_bfloat16 g_w[(size_t)NPAD * Kc];     // exp(-dist) numerators, ~197MB
__device__ __nv_bfloat16 g_zt[(size_t)NPAD * Dc];    // -2*z bf16, row-major [N][512]
__device__ __nv_bfloat16 g_cbt[(size_t)Kc * Dc];     // bf16 codebook [K][512]
__device__ float g_Z[Nc];
__device__ float g_z2[Nc];
__device__ float g_c2[Kc];
__device__ int   g_nvalid[Bc];
__device__ float g_partial[NCHUNKS][Kc];
__device__ float g_cd[Kc];

// ---------------- helpers ----------------
__device__ __forceinline__ uint32_t smem_u32(const void* p) {
    uint32_t a;
    asm("{ .reg .u64 t; cvta.to.shared.u64 t, %1; cvt.u32.u64 %0, t; }" : "=r"(a) : "l"(p));
    return a;
}
__device__ __forceinline__ uint32_t swz(uint32_t off) { return off ^ ((off >> 3) & 0x70); }
__device__ __forceinline__ float fsqrt_ap(float x) {
    float r; asm("sqrt.approx.ftz.f32 %0, %1;" : "=f"(r) : "f"(x)); return r;
}
__device__ __forceinline__ float fex2_ap(float x) {
    float r; asm("ex2.approx.ftz.f32 %0, %1;" : "=f"(r) : "f"(x)); return r;
}

#define CP_ASYNC16(dst, src) \
    asm volatile("cp.async.cg.shared.global [%0], [%1], 16;" :: "r"(dst), "l"(src))
#define CP_COMMIT() asm volatile("cp.async.commit_group;")
#define CP_WAIT(n)  asm volatile("cp.async.wait_group %0;" :: "n"(n))

#define LDSM4(R, addr) \
    asm volatile("ldmatrix.sync.aligned.m8n8.x4.shared.b16 {%0,%1,%2,%3}, [%4];" \
        : "=r"((R)[0]), "=r"((R)[1]), "=r"((R)[2]), "=r"((R)[3]) : "r"(addr))

#define MMA_BF16(C, A, b0, b1) \
    asm volatile("mma.sync.aligned.m16n8k16.row.col.f32.bf16.bf16.f32 " \
        "{%0,%1,%2,%3}, {%4,%5,%6,%7}, {%8,%9}, {%0,%1,%2,%3};" \
        : "+f"((C)[0]), "+f"((C)[1]), "+f"((C)[2]), "+f"((C)[3]) \
        : "r"((A)[0]), "r"((A)[1]), "r"((A)[2]), "r"((A)[3]), "r"(b0), "r"(b1))

// ---------------- kernel 0: init ----------------
__global__ void k_init(const void* lenp, const void* stridep) {
    int i = blockIdx.x * blockDim.x + threadIdx.x;
    int total = blockDim.x * gridDim.x;
    for (int n = i; n < Nc; n += total) { g_Z[n] = 0.f; g_z2[n] = 0.f; }
    const __nv_bfloat16 zb = __float2bfloat16(0.f);
    for (int j = i; j < (NPAD - Nc) * Dc; j += total) g_zt[(size_t)Nc * Dc + j] = zb;
    if (i == 0) {
        long long s = 320;
        if (stridep) {
            long long v = *(const long long*)stridep;
            if (v > 0 && v < (1ll << 31)) s = v;
            else { int v32 = *(const int*)stridep; if (v32 > 0) s = v32; }
        }
        const long long* l64 = (const long long*)lenp;
        const int*       l32 = (const int*)lenp;
        bool is64 = true;
        for (int b = 0; b < Bc; b++) {
            long long v = l64[b];
            if (v < 0 || v >= (1ll << 31)) { is64 = false; break; }
        }
        for (int b = 0; b < Bc; b++) {
            long long L = is64 ? l64[b] : (long long)l32[b];
            long long nv = L / s;
            if (nv > Tc) nv = Tc;
            if (nv < 0) nv = 0;
            g_nvalid[b] = (int)nv;
        }
    }
}

// ---------------- transpose feat -> g_zt = bf16(-2*z), fused z2 ----------------
__global__ void k_prep(const float* __restrict__ feat) {
    __shared__ float tile[32][33];
    __shared__ float sz[32];
    int b  = blockIdx.z;
    int d0 = blockIdx.y * 32;
    int t0 = blockIdx.x * 32;
    int tx = threadIdx.x & 31;
    int ty = threadIdx.x >> 5;
    if (threadIdx.x < 32) sz[threadIdx.x] = 0.f;
    __syncthreads();
    const float* src = feat + (size_t)b * Dc * Tc;
    float ssq = 0.f;
    #pragma unroll
    for (int j = 0; j < 4; j++) {
        int d = d0 + ty + j * 8, t = t0 + tx;
        float v = (t < Tc) ? src[(size_t)d * Tc + t] : 0.f;
        tile[ty + j * 8][tx] = v;
        ssq += v * v;
    }
    atomicAdd(&sz[tx], ssq);
    __syncthreads();
    #pragma unroll
    for (int j = 0; j < 4; j++) {
        int t = t0 + ty + j * 8, d = d0 + tx;
        if (t < Tc)
            g_zt[(size_t)(b * Tc + t) * Dc + d] = __float2bfloat16(-2.f * tile[tx][ty + j * 8]);
    }
    if (ty == 0) {
        int t = t0 + tx;
        if (t < Tc) atomicAdd(&g_z2[b * Tc + t], sz[tx]);
    }
}

// ---------------- c2 + bf16 codebook copy (float4 vectorized) ----------------
__global__ void k_c2(const float* __restrict__ cb) {
    int warp = (blockIdx.x * blockDim.x + threadIdx.x) >> 5;
    int lane = threadIdx.x & 31;
    if (warp >= Kc) return;
    const float* r = cb + (size_t)warp * Dc;
    __nv_bfloat16* w = g_cbt + (size_t)warp * Dc;
    float s = 0.f;
    #pragma unroll
    for (int it = 0; it < 4; it++) {
        int d = it * 128 + lane * 4;
        float4 v = *(const float4*)(r + d);
        s += v.x * v.x + v.y * v.y + v.z * v.z + v.w * v.w;
        __nv_bfloat162 p0 = __floats2bfloat162_rn(v.x, v.y);
        __nv_bfloat162 p1 = __floats2bfloat162_rn(v.z, v.w);
        uint2 st = make_uint2(*(uint32_t*)&p0, *(uint32_t*)&p1);
        *(uint2*)(w + d) = st;
    }
    #pragma unroll
    for (int o = 16; o; o >>= 1) s += __shfl_down_sync(0xffffffffu, s, o);
    if (lane == 0) g_c2[warp] = s;
}

// ---------------- cp.async stage issue ----------------
__device__ __forceinline__ void issue_stage(uint32_t sb, int kc, int n0, int k0, int tid) {
    uint32_t sbase = sb + (uint32_t)(kc & 1) * STAGE;
    int kcol = kc * 64;
    #pragma unroll
    for (int i = 0; i < 4; i++) {
        int id = i * 256 + tid;
        int row = id >> 3, ch = id & 7;
        const void* src = &g_zt[(size_t)(n0 + row) * Dc + kcol + ch * 8];
        uint32_t dst = sbase + swz((uint32_t)(row * 128 + ch * 16));
        CP_ASYNC16(dst, src);
    }
    #pragma unroll
    for (int i = 0; i < 4; i++) {
        int id = i * 256 + tid;
        int row = id >> 3, ch = id & 7;
        const void* src = &g_cbt[(size_t)(k0 + row) * Dc + kcol + ch * 8];
        uint32_t dst = sbase + 16384u + swz((uint32_t)(row * 128 + ch * 16));
        CP_ASYNC16(dst, src);
    }
    CP_COMMIT();
}

// ---------------- bf16 mma GEMM + fused softmax-numerator epilogue ----------------
// CTA 128x128, 8 warps in 2x4. Warp tile 64x32. 2-stage cp.async, ONE sync/stage.
__global__ __launch_bounds__(256, 2)
void k_gemm_mma() {
    extern __shared__ __align__(1024) char smem[];
    const uint32_t sb = smem_u32(smem);
    const int tid  = threadIdx.x;
    const int warp = tid >> 5;
    const int lane = tid & 31;
    const int k0 = blockIdx.x * COLB;
    const int n0 = blockIdx.y * ROWB;

    // sync-free CTA skip: valid rows are a prefix of each batch, and a
    // 128-row block spans at most 2 batches.
    {
        int b0 = n0 / Tc, t0 = n0 - b0 * Tc;
        bool any = (t0 < g_nvalid[b0]);
        if (!any && (t0 + ROWB > Tc) && (b0 + 1 < Bc)) any = (g_nvalid[b0 + 1] > 0);
        if (!any) return;
    }

    issue_stage(sb, 0, n0, k0, tid);

    const int wr = warp >> 2;      // 0..1
    const int wc = warp & 3;       // 0..3
    const int g  = lane >> 3;      // 0..3 (ldmatrix address group)
    const int lr = lane & 7;

    uint32_t aoff[4], boff[2];
    {
        int arow  = wr * 64 + (g & 1) * 8 + lr;
        int acolb = (g >> 1) * 16;
        #pragma unroll
        for (int mt = 0; mt < 4; mt++)
            aoff[mt] = swz((uint32_t)((arow + mt * 16) * 128 + acolb));
        int bcolb = (g & 1) * 16;
        #pragma unroll
        for (int p = 0; p < 2; p++) {
            int brow = wc * 32 + p * 16 + (g >> 1) * 8 + lr;
            boff[p] = 16384u + swz((uint32_t)(brow * 128 + bcolb));
        }
    }

    float acc[4][4][4];
    #pragma unroll
    for (int mt = 0; mt < 4; mt++)
        #pragma unroll
        for (int nt = 0; nt < 4; nt++)
            #pragma unroll
            for (int q = 0; q < 4; q++) acc[mt][nt][q] = 0.f;

    #pragma unroll 1
    for (int kc = 0; kc < NKCH; kc++) {
        CP_WAIT(0);            // stage kc is the only group in flight
        __syncthreads();       // publishes stage kc; proves compute kc-1 done
        if (kc + 1 < NKCH) issue_stage(sb, kc + 1, n0, k0, tid);  // safe post-sync
        uint32_t sbase = sb + (uint32_t)(kc & 1) * STAGE;
        #pragma unroll
        for (int ks = 0; ks < 4; ks++) {
            // k-step advance XORed into swizzled address (carry-free):
            // swz(off + ks*32) == swz(off) ^ (ks*32).
            const uint32_t kx = (uint32_t)(ks * 32);
            uint32_t A[4][4], B[2][4];
            #pragma unroll
            for (int mt = 0; mt < 4; mt++) LDSM4(A[mt], sbase + (aoff[mt] ^ kx));
            #pragma unroll
            for (int p = 0; p < 2; p++)    LDSM4(B[p],  sbase + (boff[p] ^ kx));
            #pragma unroll
            for (int mt = 0; mt < 4; mt++)
                #pragma unroll
                for (int nt = 0; nt < 4; nt++)
                    MMA_BF16(acc[mt][nt], A[mt], B[nt >> 1][(nt & 1) * 2], B[nt >> 1][(nt & 1) * 2 + 1]);
        }
    }

    // ---- fused epilogue: w = ex2(-log2e * sqrt(max(z2 + c2 + acc, 1e-12))) ----
    const float NLOG2E = -1.4426950408889634f;
    const int rowq = lane >> 2;           // 0..7
    const int colp = (lane & 3) * 2;
    #pragma unroll
    for (int mt = 0; mt < 4; mt++) {
        int r0 = n0 + wr * 64 + mt * 16 + rowq;
        int r1 = r0 + 8;
        int b0i = r0 / Tc, t0i = r0 - b0i * Tc;
        int b1i = r1 / Tc, t1i = r1 - b1i * Tc;
        bool v0 = (r0 < Nc) && (t0i < g_nvalid[b0i]);
        bool v1 = (r1 < Nc) && (t1i < g_nvalid[b1i]);
        float z20 = v0 ? g_z2[r0] : 0.f;
        float z21 = v1 ? g_z2[r1] : 0.f;
        float rs0 = 0.f, rs1 = 0.f;
        #pragma unroll
        for (int nt = 0; nt < 4; nt++) {
            int col = k0 + wc * 32 + nt * 8 + colp;
            float2 c2 = *(const float2*)&g_c2[col];
            if (v0) {
                float d2a = fmaxf(z20 + c2.x + acc[mt][nt][0], 1e-12f);
                float d2b = fmaxf(z20 + c2.y + acc[mt][nt][1], 1e-12f);
                float w0 = fex2_ap(NLOG2E * fsqrt_ap(d2a));
                float w1 = fex2_ap(NLOG2E * fsqrt_ap(d2b));
                rs0 += w0 + w1;
                __nv_bfloat162 pk = __floats2bfloat162_rn(w0, w1);
                *(__nv_bfloat162*)&g_w[(size_t)r0 * Kc + col] = pk;
            }
            if (v1) {
                float d2a = fmaxf(z21 + c2.x + acc[mt][nt][2], 1e-12f);
                float d2b = fmaxf(z21 + c2.y + acc[mt][nt][3], 1e-12f);
                float w0 = fex2_ap(NLOG2E * fsqrt_ap(d2a));
                float w1 = fex2_ap(NLOG2E * fsqrt_ap(d2b));
                rs1 += w0 + w1;
                __nv_bfloat162 pk = __floats2bfloat162_rn(w0, w1);
                *(__nv_bfloat162*)&g_w[(size_t)r1 * Kc + col] = pk;
            }
        }
        rs0 += __shfl_xor_sync(0xffffffffu, rs0, 1);
        rs0 += __shfl_xor_sync(0xffffffffu, rs0, 2);
        rs1 += __shfl_xor_sync(0xffffffffu, rs1, 1);
        rs1 += __shfl_xor_sync(0xffffffffu, rs1, 2);
        if ((lane & 3) == 0) {
            if (v0) atomicAdd(&g_Z[r0], rs0);
            if (v1) atomicAdd(&g_Z[r1], rs1);
        }
    }
}

// ---------------- column reduce: batch-aligned chunks, prefix early-exit ----------------
__global__ void k_colreduce() {
    int k2 = blockIdx.x * blockDim.x + threadIdx.x;   // bf16x2 pair index, 0..2047
    int chunk = blockIdx.y;                            // 0..159
    int b  = chunk / CPB;
    int t0 = (chunk - b * CPB) * RCHUNK;
    int nv = g_nvalid[b];
    int tend = nv - t0;
    if (tend > RCHUNK) tend = RCHUNK;
    float ax = 0.f, ay = 0.f;
    int n = b * Tc + t0;
    #pragma unroll 4
    for (int i = 0; i < tend; i++, n++) {
        __nv_bfloat162 w2 = ((const __nv_bfloat162*)&g_w[(size_t)n * Kc])[k2];
        float2 f = __bfloat1622float2(w2);
        float iz = __fdividef(1.f, g_Z[n]);
        ax += f.x * iz;
        ay += f.y * iz;
    }
    g_partial[chunk][k2 * 2]     = ax;
    g_partial[chunk][k2 * 2 + 1] = ay;
}

// ---------------- parallel chunk reduction: cd[k] = sum_c partial[c][k] ----------------
__global__ void k_reduce_cd() {
    int k = blockIdx.x * blockDim.x + threadIdx.x;   // 4096 threads
    float s = 0.f;
    #pragma unroll 8
    for (int c = 0; c < NCHUNKS; c++) s += g_partial[c][k];
    g_cd[k] = s;
}

// ---------------- final entropy (reads only 16KB) ----------------
__device__ __forceinline__ float blockSum(float v) {
    __shared__ float sh[32];
    int lane = threadIdx.x & 31, w = threadIdx.x >> 5;
    #pragma unroll
    for (int o = 16; o; o >>= 1) v += __shfl_down_sync(0xffffffffu, v, o);
    if (!lane) sh[w] = v;
    __syncthreads();
    float r = 0.f;
    if (w == 0) {
        r = (lane < (blockDim.x >> 5)) ? sh[lane] : 0.f;
        #pragma unroll
        for (int o = 16; o; o >>= 1) r += __shfl_down_sync(0xffffffffu, r, o);
        if (!lane) sh[0] = r;
    }
    __syncthreads();
    float out = sh[0];
    __syncthreads();
    return out;
}

__global__ void k_final(float* out) {
    const int tid = threadIdx.x;   // 1024
    float cd[4];
    #pragma unroll
    for (int j = 0; j < 4; j++) cd[j] = g_cd[tid + j * 1024];
    float tot = (cd[0] + cd[1]) + (cd[2] + cd[3]);
    float S = blockSum(tot);
    float denom = S + 1e-8f;
    float e = 0.f;
    #pragma unroll
    for (int j = 0; j < 4; j++) {
        float p = cd[j] / denom;
        e += p * logf(p + 1e-8f);
    }
    float E = blockSum(e);
    if (tid == 0) out[0] = 1.f + E / logf((float)Kc);
}

// ---------------- launch ----------------
extern "C" void kernel_launch(void* const* d_in, const int* in_sizes, int n_in,
                              void* d_out, int out_size) {
    const float* feat = (const float*)d_in[0];
    const float* cb   = (const float*)d_in[1];
    const void*  lenp = d_in[2];
    const void*  stridep = (n_in > 3) ? d_in[3] : nullptr;

    cudaFuncSetAttribute(k_gemm_mma, cudaFuncAttributeMaxDynamicSharedMemorySize, SMEM_BYTES);

    k_init<<<94, 256>>>(lenp, stridep);
    dim3 gp((Tc + 31) / 32, Dc / 32, Bc);   // 47 x 16 x 16
    k_prep<<<gp, 256>>>(feat);
    k_c2<<<Kc / 8, 256>>>(cb);

    dim3 gg(NCB, NRB);                       // 32 x 188
    k_gemm_mma<<<gg, 256, SMEM_BYTES>>>();

    dim3 gr(Kc / 512, NCHUNKS);              // 8 x 160 (bf16x2 pairs, batch-aligned)
    k_colreduce<<<gr, 256>>>();
    k_reduce_cd<<<16, 256>>>();
    k_final<<<1, 1024>>>((float*)d_out);
    (void)in_sizes; (void)out_size;
}